// round 8
// baseline (speedup 1.0000x reference)
#include <cuda_runtime.h>

#define NPTS 2097152
#define NSTK 500
#define G    32
#define NC   (G*G*G)            // 32768 cells
#define WTASK 64                // points per warp-task
#define MAXT 81920
#define MAXL 192

using ull = unsigned long long;

// ---- packed f32x2 helpers (sm_103a) ----
__device__ __forceinline__ ull pk2(float lo, float hi) {
    ull r; asm("mov.b64 %0, {%1, %2};" : "=l"(r) : "f"(lo), "f"(hi)); return r;
}
__device__ __forceinline__ void up2(ull v, float& a, float& b) {
    asm("mov.b64 {%0, %1}, %2;" : "=f"(a), "=f"(b) : "l"(v));
}
__device__ __forceinline__ ull add2(ull a, ull b) {
    ull r; asm("add.rn.f32x2 %0, %1, %2;" : "=l"(r) : "l"(a), "l"(b)); return r;
}
__device__ __forceinline__ ull mul2(ull a, ull b) {
    ull r; asm("mul.rn.f32x2 %0, %1, %2;" : "=l"(r) : "l"(a), "l"(b)); return r;
}
__device__ __forceinline__ ull fma2(ull a, ull b, ull c) {
    ull r; asm("fma.rn.f32x2 %0, %1, %2, %3;" : "=l"(r) : "l"(a), "l"(b), "l"(c)); return r;
}
__device__ __forceinline__ float sqapx(float x) {
    float r; asm("sqrt.approx.f32 %0, %1;" : "=f"(r) : "f"(x)); return r;
}

#define ONE2   0x3f8000003f800000ull
#define NEG12  0xbf800000bf800000ull

// ---- scratch (device globals; zero-initialized at load) ----
__device__ float4      g_sorted[NPTS];       // wx,wy,wz, origidx-as-bits
__device__ int         g_hist[NC];           // INVARIANT: zero at entry to k_fused
__device__ int         g_cursor[NC];
__device__ int         g_cellCnt[NC];
__device__ float4      g_init4[NC];          // truncation init (d, r, g, b)
__device__ float       g_initw[NC];          // truncation init weight (0 or 1)
__device__ int         g_cellList[NC * MAXL];// CONTIGUOUS per cell: [c*MAXL + j]
__device__ ulonglong2  g_spk[NSTK * 4];      // packed stroke params
__device__ int4        g_tasks[MAXT];
__device__ int         g_taskCount;
__device__ int         g_fetch;

__device__ __forceinline__ int cellOf(float x, float y, float z) {
    int ix = min(max(__float2int_rd((x + 1.0f) * 16.0f), 0), G - 1);
    int iy = min(max(__float2int_rd((y + 1.0f) * 16.0f), 0), G - 1);
    int iz = min(max(__float2int_rd((z + 1.0f) * 16.0f), 0), G - 1);
    return ix | (iy << 5) | (iz << 10);
}

__device__ __forceinline__ void warp_pt(float x, float y, float z,
                                        float& wx, float& wy, float& wz) {
    float n2 = fmaf(x, x, fmaf(y, y, z * z));
    float n  = fmaxf(sqrtf(n2), 1e-9f);
    float sc = 0.5f;
    if (n > 1.0f) sc = (2.0f - 1.0f / n) / n * 0.5f;
    wx = x * sc; wy = y * sc; wz = z * sc;
}

// ---------- K0 (fused): blocks [0,128): cull+prep per cell; blocks [128,2176): hist per point ----------
// NOTE: does NOT zero g_hist (that would race with the hist blocks). g_hist is
// zeroed by k_scanTasks after it consumes the counts, restoring the invariant
// for the next run. g_taskCount/g_fetch are safe to reset here: consumed only
// by later launches.
#define CULLBLKS (NC / 256)          // 128
#define HISTBLKS (NPTS / (4 * 256))  // 2048

__global__ void __launch_bounds__(256)
k_fused(const float* __restrict__ shape,
        const float* __restrict__ color,
        const float* __restrict__ alpha,
        const float* __restrict__ coords,
        float* __restrict__ out) {
    if (blockIdx.x < CULLBLKS) {
        int c = blockIdx.x * blockDim.x + threadIdx.x;   // one thread per cell
        if (c == 0) { g_taskCount = 0; g_fetch = 0; }
        if (c < NSTK) {
            int s = c;
            float cx = shape[4 * s + 0], cy = shape[4 * s + 1];
            float cz = shape[4 * s + 2], r = shape[4 * s + 3];
            float A  = fmaf(5.0f, r, 0.5f);
            float B2 = (A * 0.2f) * (A * 0.2f);
            float d  = fmaxf(alpha[s], 0.0f) * 50.0f;
            float cr = color[3 * s + 0], cg = color[3 * s + 1], cb = color[3 * s + 2];
            g_spk[4 * s + 0] = make_ulonglong2(pk2(-cx, -cx), pk2(-cy, -cy));
            g_spk[4 * s + 1] = make_ulonglong2(pk2(-cz, -cz), pk2(A, B2));
            g_spk[4 * s + 2] = make_ulonglong2(pk2(d, d),     pk2(cr, cr));
            g_spk[4 * s + 3] = make_ulonglong2(pk2(cg, cg),   pk2(cb, cb));
        }

        int ix = c & 31, iy = (c >> 5) & 31, iz = c >> 10;
        const float cs = 0.0625f;
        float lox = -1.0f + ix * cs, hix = lox + cs;
        float loy = -1.0f + iy * cs, hiy = loy + cs;
        float loz = -1.0f + iz * cs, hiz = loz + cs;
        int cnt = 0;
        int lastFull = -1;
        int* __restrict__ myList = &g_cellList[c * MAXL];
        for (int s = 0; s < NSTK; s++) {
            float4 sp = *(const float4*)&shape[4 * s];     // cx,cy,cz,r
            float R = sp.w + 0.1f + 1e-4f;
            float dx = fmaxf(fmaxf(lox - sp.x, sp.x - hix), 0.0f);
            float dy = fmaxf(fmaxf(loy - sp.y, sp.y - hiy), 0.0f);
            float dz = fmaxf(fmaxf(loz - sp.z, sp.z - hiz), 0.0f);
            float d2 = fmaf(dx, dx, fmaf(dy, dy, dz * dz));
            if (d2 < R * R) {
                float fx = fmaxf(sp.x - lox, hix - sp.x);
                float fy = fmaxf(sp.y - loy, hiy - sp.y);
                float fz = fmaxf(sp.z - loz, hiz - sp.z);
                float f2 = fmaf(fx, fx, fmaf(fy, fy, fz * fz));
                float Rin = sp.w - 0.1f - 1e-3f;
                if (Rin > 0.0f && f2 < Rin * Rin) {
                    lastFull = s;
                    cnt = 0;
                } else if (cnt < MAXL) {
                    myList[cnt++] = s;
                }
            }
        }
        g_cellCnt[c] = cnt;
        if (lastFull >= 0) {
            int s = lastFull;
            g_init4[c] = make_float4(fmaxf(alpha[s], 0.0f) * 50.0f,
                                     color[3 * s + 0], color[3 * s + 1], color[3 * s + 2]);
            g_initw[c] = 0.0f;
        } else {
            g_init4[c] = make_float4(0.f, 0.f, 0.f, 0.f);
            g_initw[c] = 1.0f;
        }
    } else {
        const int t = (blockIdx.x - CULLBLKS) * blockDim.x + threadIdx.x;
        const float4* c4 = (const float4*)coords;
        float4 a = c4[3 * t + 0], b = c4[3 * t + 1], c = c4[3 * t + 2];
        float px[4] = { a.x, a.w, b.z, c.y };
        float py[4] = { a.y, b.x, b.w, c.z };
        float pz[4] = { a.z, b.y, c.x, c.w };
        float wxo[4], wyo[4], wzo[4];
#pragma unroll
        for (int i = 0; i < 4; i++) {
            warp_pt(px[i], py[i], pz[i], wxo[i], wyo[i], wzo[i]);
            atomicAdd(&g_hist[cellOf(wxo[i], wyo[i], wzo[i])], 1);
        }
        float4* o4 = (float4*)(out + 4 * NPTS);
        o4[3 * t + 0] = make_float4(wxo[0], wyo[0], wzo[0], wxo[1]);
        o4[3 * t + 1] = make_float4(wyo[1], wzo[1], wxo[2], wyo[2]);
        o4[3 * t + 2] = make_float4(wzo[2], wxo[3], wyo[3], wzo[3]);
    }
}

// ---------- K1: scan over 32768 cells + warp-task building; re-zeros g_hist ----------
__global__ void __launch_bounds__(1024, 1)
k_scanTasks() {
    __shared__ int warpsum[32];
    int tid = threadIdx.x;
    int lane = tid & 31, wid = tid >> 5;
    int base = tid * 32;
    int v[32];
    int s = 0;
#pragma unroll
    for (int k = 0; k < 32; k++) { v[k] = g_hist[base + k]; s += v[k]; }
#pragma unroll
    for (int k = 0; k < 32; k++) g_hist[base + k] = 0;   // restore invariant for next run
    int ps = s;
#pragma unroll
    for (int off = 1; off < 32; off <<= 1) {
        int t = __shfl_up_sync(0xffffffff, ps, off);
        if (lane >= off) ps += t;
    }
    if (lane == 31) warpsum[wid] = ps;
    __syncthreads();
    if (wid == 0) {
        int w = warpsum[lane];
        int pw = w;
#pragma unroll
        for (int off = 1; off < 32; off <<= 1) {
            int t = __shfl_up_sync(0xffffffff, pw, off);
            if (lane >= off) pw += t;
        }
        warpsum[lane] = pw - w;
    }
    __syncthreads();
    int o = warpsum[wid] + ps - s;
#pragma unroll
    for (int k = 0; k < 32; k++) {
        int c = base + k;
        g_cursor[c] = o;
        int np = v[k];
        if (np > 0) {
            int nt = (np + WTASK - 1) / WTASK;
            int b = atomicAdd(&g_taskCount, nt);
            for (int q = 0; q < nt; q++) {
                int a = o + q * WTASK;
                int e = min(o + np, a + WTASK);
                g_tasks[b + q] = make_int4(c, a, e, 0);
            }
        }
        o += np;
    }
}

// ---------- K2: recompute warp, scatter into cell-sorted order ----------
__global__ void __launch_bounds__(256)
k_scatter(const float* __restrict__ coords) {
    const int t = blockIdx.x * blockDim.x + threadIdx.x;
    const float4* c4 = (const float4*)coords;
    float4 a = c4[3 * t + 0], b = c4[3 * t + 1], c = c4[3 * t + 2];
    float px[4] = { a.x, a.w, b.z, c.y };
    float py[4] = { a.y, b.x, b.w, c.z };
    float pz[4] = { a.z, b.y, c.x, c.w };
#pragma unroll
    for (int i = 0; i < 4; i++) {
        float wx, wy, wz;
        warp_pt(px[i], py[i], pz[i], wx, wy, wz);
        int cc = cellOf(wx, wy, wz);
        int pos = atomicAdd(&g_cursor[cc], 1);
        g_sorted[pos] = make_float4(wx, wy, wz, __int_as_float(4 * t + i));
    }
}

// ---------- K3: persistent main blend, warp-granularity tasks ----------
__global__ void __launch_bounds__(128)
k_main(float* __restrict__ out) {
    const int lane = threadIdx.x & 31;
    const int nTasks = g_taskCount;

    for (;;) {
        int tkid;
        if (lane == 0) tkid = atomicAdd(&g_fetch, 1);
        tkid = __shfl_sync(0xffffffffu, tkid, 0);
        if (tkid >= nTasks) return;
        int4 tk = g_tasks[tkid];
        const int cell = tk.x, start = tk.y, end = tk.z;
        const int m = g_cellCnt[cell];
        const int* __restrict__ list = &g_cellList[cell * MAXL];

        const int q0 = start + lane * 2;
        const int q1 = q0 + 1;
        const bool ok0 = q0 < end, ok1 = q1 < end;
        float4 pa = ok0 ? g_sorted[q0] : make_float4(9.f, 9.f, 9.f, 0.f);
        float4 pb = ok1 ? g_sorted[q1] : make_float4(9.f, 9.f, 9.f, 0.f);

        ull cxx = pk2(pa.x, pb.x);
        ull cyy = pk2(pa.y, pb.y);
        ull czz = pk2(pa.z, pb.z);

        float4 iv = g_init4[cell];
        float  iw = g_initw[cell];
        ull hd = pk2(iv.x, iv.x);
        ull hr = pk2(iv.y, iv.y);
        ull hg = pk2(iv.z, iv.z);
        ull hb = pk2(iv.w, iv.w);
        ull hw = pk2(iw, iw);

        // software-pipelined: prefetch next stroke while blending current
        ulonglong2 v0, v1, v2, v3;
        if (m > 0) {
            int s = list[0];
            v0 = g_spk[4 * s + 0]; v1 = g_spk[4 * s + 1];
            v2 = g_spk[4 * s + 2]; v3 = g_spk[4 * s + 3];
        }
        for (int j = 0; j < m; j++) {
            ulonglong2 n0, n1, n2, n3;
            if (j + 1 < m) {
                int s = list[j + 1];
                n0 = g_spk[4 * s + 0]; n1 = g_spk[4 * s + 1];
                n2 = g_spk[4 * s + 2]; n3 = g_spk[4 * s + 3];
            }
            float A, B2; up2(v1.y, A, B2);
            ull dx = add2(cxx, v0.x);
            ull dy = add2(cyy, v0.y);
            ull dz = add2(czz, v1.x);
            ull d2 = mul2(dx, dx);
            d2 = fma2(dy, dy, d2);
            d2 = fma2(dz, dz, d2);
            float qa, qb; up2(d2, qa, qb);
            bool act = (qa < B2) | (qb < B2);
            if (__ballot_sync(0xffffffffu, act)) {
                float t0 = __saturatef(fmaf(sqapx(qa), -5.0f, A));
                float t1 = __saturatef(fmaf(sqapx(qb), -5.0f, A));
                ull t2  = pk2(t0, t1);
                ull omt = fma2(t2, NEG12, ONE2);
                hd = fma2(t2, v2.x, mul2(omt, hd));
                hr = fma2(t2, v2.y, mul2(omt, hr));
                hg = fma2(t2, v3.x, mul2(omt, hg));
                hb = fma2(t2, v3.y, mul2(omt, hb));
                hw = mul2(omt, hw);
            }
            v0 = n0; v1 = n1; v2 = n2; v3 = n3;
        }

        float d0, d1, w0, w1, r0, r1, g0, g1, b0, b1;
        up2(hd, d0, d1);
        up2(hw, w0, w1);
        up2(hr, r0, r1);
        up2(hg, g0, g1);
        up2(hb, b0, b1);
        if (ok0) {
            int oi = __float_as_int(pa.w);
            float inv = 1.0f / (1.0f + 1e-6f - w0);
            out[oi] = d0;
            out[NPTS + 3 * oi + 0] = __saturatef(r0 * inv);
            out[NPTS + 3 * oi + 1] = __saturatef(g0 * inv);
            out[NPTS + 3 * oi + 2] = __saturatef(b0 * inv);
        }
        if (ok1) {
            int oi = __float_as_int(pb.w);
            float inv = 1.0f / (1.0f + 1e-6f - w1);
            out[oi] = d1;
            out[NPTS + 3 * oi + 0] = __saturatef(r1 * inv);
            out[NPTS + 3 * oi + 1] = __saturatef(g1 * inv);
            out[NPTS + 3 * oi + 2] = __saturatef(b1 * inv);
        }
    }
}

extern "C" void kernel_launch(void* const* d_in, const int* in_sizes, int n_in,
                              void* d_out, int out_size)
{
    const float* coords = (const float*)d_in[0];
    const float* shape  = (const float*)d_in[1];
    const float* color  = (const float*)d_in[2];
    const float* alpha  = (const float*)d_in[3];
    float* out = (float*)d_out;

    k_fused<<<CULLBLKS + HISTBLKS, 256>>>(shape, color, alpha, coords, out);  // 0
    k_scanTasks<<<1, 1024>>>();                                               // 1
    k_scatter<<<NPTS / (4 * 256), 256>>>(coords);                             // 2
    k_main<<<1184, 128>>>(out);                                               // 3 (ncu samples idx 3)
}